// round 12
// baseline (speedup 1.0000x reference)
#include <cuda_runtime.h>
#include <math.h>
#include <cstdint>

// Problem constants
#define S_LEN 2048
#define D_MODEL 2048
#define NB 2
#define NH 16
#define HDIM 128
#define BH (NB*NH)
#define HALF_HD 64

// ---------------------------------------------------------------------------
// Scratch
// ---------------------------------------------------------------------------
__device__ float g_q  [NB*S_LEN*D_MODEL];       // d-PERMUTED within 8-groups
__device__ float g_k  [NB*S_LEN*D_MODEL];       // d-PERMUTED within 8-groups
__device__ float g_vt [BH*HDIM*S_LEN];          // V^T per (b,h); s-PERMUTED within 8-groups
__device__ float g_att[NB*S_LEN*D_MODEL];       // doubles as tf32-rounded x (K-PERMUTED)
__device__ float g_wt [4*D_MODEL*D_MODEL];      // W^T (tf32-rounded, K-PERMUTED)
__device__ float g_cos[S_LEN*HALF_HD];
__device__ float g_sin[S_LEN*HALF_HD];

// ---------------------------------------------------------------------------
// Helpers
// ---------------------------------------------------------------------------
__device__ __forceinline__ float tf32r(float x) {
    uint32_t u = __float_as_uint(x);
    asm("cvt.rna.tf32.f32 %0, %1;" : "=r"(u) : "r"(u));
    return __uint_as_float(u);
}

// Permutation within each 8-group: col j -> (j<4 ? 2j : 2j-7).
// Position 2q holds col q; position 2q+1 holds col q+4 -> LDS.64 frag pairs.
__device__ __forceinline__ int kperm(int j) {
    return (j < 4) ? (2 * j) : (2 * j - 7);
}

__device__ __forceinline__ uint32_t smem_u32(const void* p) {
    uint32_t a;
    asm("{ .reg .u64 t; cvta.to.shared.u64 t, %1; cvt.u32.u64 %0, t; }"
        : "=r"(a) : "l"(p));
    return a;
}

__device__ __forceinline__ void cp16(uint32_t dst, const float* src) {
    asm volatile("cp.async.cg.shared.global [%0], [%1], 16;" :: "r"(dst), "l"(src));
}
__device__ __forceinline__ void cp_commit() {
    asm volatile("cp.async.commit_group;");
}
template<int N>
__device__ __forceinline__ void cp_wait() {
    asm volatile("cp.async.wait_group %0;" :: "n"(N));
}

__device__ __forceinline__ void mma_tf32(float* c, const uint32_t* a, const uint32_t* b) {
    asm volatile(
        "mma.sync.aligned.m16n8k8.row.col.f32.tf32.tf32.f32 "
        "{%0,%1,%2,%3}, {%4,%5,%6,%7}, {%8,%9}, {%0,%1,%2,%3};"
        : "+f"(c[0]), "+f"(c[1]), "+f"(c[2]), "+f"(c[3])
        : "r"(a[0]), "r"(a[1]), "r"(a[2]), "r"(a[3]), "r"(b[0]), "r"(b[1]));
}

// ---------------------------------------------------------------------------
// RoPE tables
// ---------------------------------------------------------------------------
__global__ void rope_tables_kernel() {
    int idx = blockIdx.x * blockDim.x + threadIdx.x;
    if (idx >= S_LEN * HALF_HD) return;
    int s = idx / HALF_HD;
    int i = idx % HALF_HD;
    float inv = expf(-((float)(2 * i) / (float)HDIM) * logf(10000.0f));
    float f = (float)s * inv;
    g_cos[idx] = cosf(f);
    g_sin[idx] = sinf(f);
}

// ---------------------------------------------------------------------------
// x -> tf32-rounded, K-permuted copy
// ---------------------------------------------------------------------------
__global__ void round_copy_kernel(const float* __restrict__ in, float* __restrict__ out, int n) {
    int i = blockIdx.x * blockDim.x + threadIdx.x;
    if (i >= n) return;
    int c = i & (D_MODEL - 1);
    int pc = (c & ~7) | kperm(c & 7);
    out[(i & ~(D_MODEL - 1)) | pc] = tf32r(in[i]);
}

// ---------------------------------------------------------------------------
// 4x 2048x2048 transpose, tf32-rounded, K-permuted output (z selects W)
// ---------------------------------------------------------------------------
__global__ void transpose4_kernel(const float* __restrict__ Wq, const float* __restrict__ Wk,
                                  const float* __restrict__ Wv, const float* __restrict__ Wo,
                                  float* __restrict__ wt) {
    __shared__ float t[32][33];
    const float* in = (blockIdx.z == 0) ? Wq : (blockIdx.z == 1) ? Wk
                     : (blockIdx.z == 2) ? Wv : Wo;
    float* out = wt + (size_t)blockIdx.z * D_MODEL * D_MODEL;
    int x = blockIdx.x * 32 + threadIdx.x;
    int y = blockIdx.y * 32 + threadIdx.y;
    #pragma unroll
    for (int j = 0; j < 32; j += 8)
        t[threadIdx.y + j][threadIdx.x] = tf32r(in[(size_t)(y + j) * D_MODEL + x]);
    __syncthreads();
    x = blockIdx.y * 32 + threadIdx.x;
    y = blockIdx.x * 32 + threadIdx.y;
    int px = (x & ~7) | kperm(x & 7);     // permute K-dim (out column)
    #pragma unroll
    for (int j = 0; j < 32; j += 8)
        out[(size_t)(y + j) * D_MODEL + px] = t[threadIdx.x][threadIdx.y + j];
}

// ---------------------------------------------------------------------------
// Shared GEMM mainloop (unchanged from R11): 128x128 tile, BK=32, 4 warps,
// warp tile 64x64. 2-stage cp.async. Operands K-PERMUTED; SROW=40 -> LDS.64
// fragment loads conflict-free. Result staged as Cs[128][CSTR].
// ---------------------------------------------------------------------------
#define SROW 40
#define TILE_F (128*SROW)
#define GEMM_SMEM_SZ (2*2*TILE_F*4)        // 81920 B
#define CSTR 132

__device__ __forceinline__ void gemm_128x128(
    const float* __restrict__ Ag, const float* __restrict__ Bg,
    float* sbase, uint32_t s_u32, int tid)
{
    const int wid = tid >> 5;
    const int lane = tid & 31;
    const int group = lane >> 2;
    const int qd = lane & 3;
    const int wm = (wid >> 1) * 64;
    const int wn = (wid & 1) * 64;
    const int lr = tid >> 3;
    const int lc4 = (tid & 7) * 4;

    float acc[4][8][4];
    #pragma unroll
    for (int mt = 0; mt < 4; mt++)
        #pragma unroll
        for (int nt = 0; nt < 8; nt++)
            #pragma unroll
            for (int i = 0; i < 4; i++) acc[mt][nt][i] = 0.0f;

    {
        uint32_t sa = s_u32;
        uint32_t sb = s_u32 + TILE_F * 4;
        #pragma unroll
        for (int i = 0; i < 8; i++) {
            int r = i * 16 + lr;
            uint32_t so = (uint32_t)(r * SROW + lc4) * 4;
            cp16(sa + so, Ag + (size_t)r * D_MODEL + lc4);
            cp16(sb + so, Bg + (size_t)r * D_MODEL + lc4);
        }
        cp_commit();
    }

    for (int ch = 0; ch < 64; ch++) {
        const int st = ch & 1;
        if (ch + 1 < 64) {
            const int k0 = (ch + 1) << 5;
            uint32_t sa = s_u32 + (uint32_t)((ch + 1) & 1) * (2 * TILE_F * 4);
            uint32_t sb = sa + TILE_F * 4;
            #pragma unroll
            for (int i = 0; i < 8; i++) {
                int r = i * 16 + lr;
                uint32_t so = (uint32_t)(r * SROW + lc4) * 4;
                cp16(sa + so, Ag + (size_t)r * D_MODEL + k0 + lc4);
                cp16(sb + so, Bg + (size_t)r * D_MODEL + k0 + lc4);
            }
            cp_commit();
            cp_wait<1>();
        } else {
            cp_wait<0>();
        }
        __syncthreads();

        const float* As = sbase + st * 2 * TILE_F;
        const float* Bs = As + TILE_F;

        #pragma unroll
        for (int kk = 0; kk < 4; kk++) {
            const int colk2 = kk * 8 + 2 * qd;
            uint32_t af[4][4], bf[8][2];
            #pragma unroll
            for (int mt = 0; mt < 4; mt++) {
                int r0 = wm + mt * 16 + group;
                float2 a0 = *(const float2*)(As + r0 * SROW + colk2);
                float2 a1 = *(const float2*)(As + (r0 + 8) * SROW + colk2);
                af[mt][0] = __float_as_uint(a0.x);
                af[mt][1] = __float_as_uint(a1.x);
                af[mt][2] = __float_as_uint(a0.y);
                af[mt][3] = __float_as_uint(a1.y);
            }
            #pragma unroll
            for (int nt = 0; nt < 8; nt++) {
                int bn = wn + nt * 8 + group;
                float2 b0 = *(const float2*)(Bs + bn * SROW + colk2);
                bf[nt][0] = __float_as_uint(b0.x);
                bf[nt][1] = __float_as_uint(b0.y);
            }
            #pragma unroll
            for (int mt = 0; mt < 4; mt++)
                #pragma unroll
                for (int nt = 0; nt < 8; nt++)
                    mma_tf32(acc[mt][nt], af[mt], bf[nt]);
        }
        __syncthreads();
    }

    float* Cs = sbase;
    #pragma unroll
    for (int mt = 0; mt < 4; mt++) {
        int r0 = wm + mt * 16 + group;
        #pragma unroll
        for (int nt = 0; nt < 8; nt++) {
            int cb = wn + nt * 8 + 2 * qd;
            Cs[r0 * CSTR + cb]           = acc[mt][nt][0];
            Cs[r0 * CSTR + cb + 1]       = acc[mt][nt][1];
            Cs[(r0 + 8) * CSTR + cb]     = acc[mt][nt][2];
            Cs[(r0 + 8) * CSTR + cb + 1] = acc[mt][nt][3];
        }
    }
    __syncthreads();
}

// ---------------------------------------------------------------------------
// QKV combined projection. z=0/1: Q/K with RoPE, written d-PERMUTED (FA frag
// layout). z=2: V^T, written s-PERMUTED. Outputs tf32-rounded.
// ---------------------------------------------------------------------------
__global__ void __launch_bounds__(128, 2)
tc_gemm_qkv(const float* __restrict__ A,
            const float* __restrict__ W0, const float* __restrict__ W1,
            const float* __restrict__ W2,
            const float* __restrict__ b0, const float* __restrict__ b1,
            const float* __restrict__ b2,
            float* __restrict__ Cq, float* __restrict__ Ck, float* __restrict__ Cv)
{
    extern __shared__ char smem_raw[];
    float* sbase = (float*)smem_raw;
    const uint32_t s_u32 = smem_u32(smem_raw);
    const int tid = threadIdx.x;
    const int z = blockIdx.z;
    const int m0 = blockIdx.y * 128;
    const int n0 = blockIdx.x * 128;

    const float* W = (z == 0) ? W0 : (z == 1) ? W1 : W2;
    const float* bias = (z == 0) ? b0 : (z == 1) ? b1 : b2;

    gemm_128x128(A + (size_t)m0 * D_MODEL, W + (size_t)n0 * D_MODEL,
                 sbase, s_u32, tid);
    const float* Cs = sbase;

    if (z < 2) {
        // RoPE epilogue into q or k, d-permuted within 8-groups
        float* C = (z == 0) ? Cq : Ck;
        #pragma unroll
        for (int i = 0; i < 64; i++) {
            int flat = i * 128 + tid;
            int row = flat >> 6;
            int ci = flat & 63;
            float v1 = Cs[row * CSTR + ci]      + __ldg(bias + n0 + ci);
            float v2 = Cs[row * CSTR + ci + 64] + __ldg(bias + n0 + ci + 64);
            int s = (m0 + row) & (S_LEN - 1);
            float cv = g_cos[s * HALF_HD + ci];
            float sv = g_sin[s * HALF_HD + ci];
            float o1 = v1 * cv - v2 * sv;
            float o2 = v1 * sv + v2 * cv;
            int c1 = n0 + ci;
            int c2 = c1 + 64;
            int p1 = (c1 & ~7) | kperm(c1 & 7);
            int p2 = (c2 & ~7) | kperm(c2 & 7);
            float* dst = C + (size_t)(m0 + row) * D_MODEL;
            dst[p1] = tf32r(o1);
            dst[p2] = tf32r(o2);
        }
    } else {
        // V^T epilogue: vt[((b*16+h)*128 + d)*S_LEN + s], s-permuted
        const int h = n0 >> 7;
        #pragma unroll
        for (int i = 0; i < 128; i++) {
            int flat = i * 128 + tid;
            int sl = flat & 127;
            int d = flat >> 7;
            float v = Cs[sl * CSTR + d] + __ldg(bias + n0 + d);
            int b = (m0 + sl) >> 11;
            int s = (m0 + sl) & (S_LEN - 1);
            int ps = (s & ~7) | kperm(s & 7);
            Cv[((size_t)(b * NH + h) * HDIM + d) * S_LEN + ps] = tf32r(v);
        }
    }
}

// ---------------------------------------------------------------------------
// Output projection: plain bias epilogue, full fp32 standard-layout output.
// ---------------------------------------------------------------------------
__global__ void __launch_bounds__(128, 2)
tc_gemm_o(const float* __restrict__ A, const float* __restrict__ W,
          const float* __restrict__ bias, float* __restrict__ C)
{
    extern __shared__ char smem_raw[];
    float* sbase = (float*)smem_raw;
    const uint32_t s_u32 = smem_u32(smem_raw);
    const int tid = threadIdx.x;
    const int m0 = blockIdx.y * 128;
    const int n0 = blockIdx.x * 128;

    gemm_128x128(A + (size_t)m0 * D_MODEL, W + (size_t)n0 * D_MODEL,
                 sbase, s_u32, tid);
    const float* Cs = sbase;

    const int col4 = (tid & 31) * 4;
    float bv[4];
    bv[0] = __ldg(bias + n0 + col4);
    bv[1] = __ldg(bias + n0 + col4 + 1);
    bv[2] = __ldg(bias + n0 + col4 + 2);
    bv[3] = __ldg(bias + n0 + col4 + 3);
    #pragma unroll
    for (int i = 0; i < 32; i++) {
        int row = (tid >> 5) + i * 4;
        const float* src = Cs + row * CSTR + col4;
        float4 v;
        v.x = src[0] + bv[0];
        v.y = src[1] + bv[1];
        v.z = src[2] + bv[2];
        v.w = src[3] + bv[3];
        *(float4*)(C + (size_t)(m0 + row) * D_MODEL + n0 + col4) = v;
    }
}

// ---------------------------------------------------------------------------
// Flash attention: per (q-tile 128, bh). q/k d-permuted, vt s-permuted ->
// ALL fragment loads are LDS.64. FA_SROW=136: float2 row stride 68 = 4 mod 16
// bank-pairs -> conflict-free. P staged s-permuted. att written K-PERMUTED.
// ---------------------------------------------------------------------------
#define FA_SROW 136
#define FA_TILE (128*FA_SROW)
#define FA_SMEM_SZ (3*FA_TILE*4)      // 208896 bytes

__global__ void __launch_bounds__(256, 1)
fa_kernel(const float* __restrict__ q, const float* __restrict__ k,
          const float* __restrict__ vt, float* __restrict__ att)
{
    extern __shared__ float sm[];
    float* sQP = sm;
    float* sK  = sm + FA_TILE;
    float* sV  = sm + 2 * FA_TILE;
    const uint32_t uQP = smem_u32(sQP);
    const uint32_t uK  = smem_u32(sK);
    const uint32_t uV  = smem_u32(sV);

    const int tid = threadIdx.x;
    const int wid = tid >> 5;
    const int lane = tid & 31;
    const int group = lane >> 2;
    const int qd = lane & 3;
    const int bh = blockIdx.y;
    const int b = bh >> 4, h = bh & 15;
    const int q0 = blockIdx.x * 128;

    const float* Qg = q + ((size_t)(b * S_LEN + q0)) * D_MODEL + h * HDIM;
    const float* Kg = k + ((size_t)b * S_LEN) * D_MODEL + h * HDIM;
    const float* Vg = vt + (size_t)bh * HDIM * S_LEN;

    #pragma unroll
    for (int i = 0; i < 16; i++) {
        int idx = i * 256 + tid;
        int r = idx >> 5, c = (idx & 31) * 4;
        cp16(uQP + (uint32_t)(r * FA_SROW + c) * 4, Qg + (size_t)r * D_MODEL + c);
    }
    cp_commit();
    #pragma unroll
    for (int i = 0; i < 16; i++) {
        int idx = i * 256 + tid;
        int r = idx >> 5, c = (idx & 31) * 4;
        cp16(uK + (uint32_t)(r * FA_SROW + c) * 4, Kg + (size_t)r * D_MODEL + c);
    }
    cp_commit();
    cp_wait<1>();
    __syncthreads();

    // Q A-fragments (d-permuted layout: float2 at 2qd = cols (qd, qd+4))
    uint32_t qa[16][4];
    {
        const float* base = sQP + (wid * 16 + group) * FA_SROW;
        #pragma unroll
        for (int kk = 0; kk < 16; kk++) {
            float2 q0v = *(const float2*)(base + kk * 8 + 2 * qd);
            float2 q1v = *(const float2*)(base + 8 * FA_SROW + kk * 8 + 2 * qd);
            qa[kk][0] = __float_as_uint(q0v.x);
            qa[kk][1] = __float_as_uint(q1v.x);
            qa[kk][2] = __float_as_uint(q0v.y);
            qa[kk][3] = __float_as_uint(q1v.y);
        }
    }
    __syncthreads();
    #pragma unroll
    for (int i = 0; i < 16; i++) {
        int idx = i * 256 + tid;
        int r = idx >> 5, c = (idx & 31) * 4;
        cp16(uV + (uint32_t)(r * FA_SROW + c) * 4, Vg + (size_t)r * S_LEN + c);
    }
    cp_commit();

    const float alpha = 0.08838834764831843f;
    float m0 = -1e30f, m1 = -1e30f, l0 = 0.0f, l1 = 0.0f;
    float oacc[16][4];
    #pragma unroll
    for (int nt = 0; nt < 16; nt++)
        #pragma unroll
        for (int i = 0; i < 4; i++) oacc[nt][i] = 0.0f;

    float* prow = sQP + (wid * 16 + group) * FA_SROW;
    const int P0 = kperm(2 * qd);         // staging pos of col 2qd
    const int P1 = kperm(2 * qd + 1);     // staging pos of col 2qd+1

    for (int it = 0; it < 16; it++) {
        cp_wait<1>();
        __syncthreads();

        // ---- S = Q @ K^T (both d-permuted; LDS.64 B-frags) ----
        float sacc[16][4];
        #pragma unroll
        for (int nt = 0; nt < 16; nt++)
            #pragma unroll
            for (int i = 0; i < 4; i++) sacc[nt][i] = 0.0f;

        #pragma unroll
        for (int kk = 0; kk < 16; kk++) {
            const int colk2 = kk * 8 + 2 * qd;
            #pragma unroll
            for (int nt = 0; nt < 16; nt++) {
                float2 b0 = *(const float2*)(sK + (nt * 8 + group) * FA_SROW + colk2);
                uint32_t bf[2] = { __float_as_uint(b0.x), __float_as_uint(b0.y) };
                mma_tf32(sacc[nt], qa[kk], bf);
            }
        }
        __syncthreads();
        if (it + 1 < 16) {
            const float* Kn = Kg + (size_t)(it + 1) * 128 * D_MODEL;
            #pragma unroll
            for (int i = 0; i < 16; i++) {
                int idx = i * 256 + tid;
                int r = idx >> 5, c = (idx & 31) * 4;
                cp16(uK + (uint32_t)(r * FA_SROW + c) * 4, Kn + (size_t)r * D_MODEL + c);
            }
            cp_commit();
        }

        // ---- online softmax ----
        float mxa = -1e30f, mxb = -1e30f;
        #pragma unroll
        for (int nt = 0; nt < 16; nt++) {
            sacc[nt][0] *= alpha; sacc[nt][1] *= alpha;
            sacc[nt][2] *= alpha; sacc[nt][3] *= alpha;
            mxa = fmaxf(mxa, fmaxf(sacc[nt][0], sacc[nt][1]));
            mxb = fmaxf(mxb, fmaxf(sacc[nt][2], sacc[nt][3]));
        }
        mxa = fmaxf(mxa, __shfl_xor_sync(0xFFFFFFFF, mxa, 1));
        mxa = fmaxf(mxa, __shfl_xor_sync(0xFFFFFFFF, mxa, 2));
        mxb = fmaxf(mxb, __shfl_xor_sync(0xFFFFFFFF, mxb, 1));
        mxb = fmaxf(mxb, __shfl_xor_sync(0xFFFFFFFF, mxb, 2));
        float na = fmaxf(m0, mxa), nb = fmaxf(m1, mxb);
        float fa_ = __expf(m0 - na), fb_ = __expf(m1 - nb);
        float psa = 0.0f, psb = 0.0f;
        #pragma unroll
        for (int nt = 0; nt < 16; nt++) {
            sacc[nt][0] = __expf(sacc[nt][0] - na);
            sacc[nt][1] = __expf(sacc[nt][1] - na);
            sacc[nt][2] = __expf(sacc[nt][2] - nb);
            sacc[nt][3] = __expf(sacc[nt][3] - nb);
            psa += sacc[nt][0] + sacc[nt][1];
            psb += sacc[nt][2] + sacc[nt][3];
        }
        psa += __shfl_xor_sync(0xFFFFFFFF, psa, 1);
        psa += __shfl_xor_sync(0xFFFFFFFF, psa, 2);
        psb += __shfl_xor_sync(0xFFFFFFFF, psb, 1);
        psb += __shfl_xor_sync(0xFFFFFFFF, psb, 2);
        l0 = l0 * fa_ + psa; l1 = l1 * fb_ + psb;
        m0 = na; m1 = nb;
        #pragma unroll
        for (int nt = 0; nt < 16; nt++) {
            oacc[nt][0] *= fa_; oacc[nt][1] *= fa_;
            oacc[nt][2] *= fb_; oacc[nt][3] *= fb_;
        }
        // stage P in s-PERMUTED layout (matches vt's s-permutation)
        #pragma unroll
        for (int nt = 0; nt < 16; nt++) {
            int cb = nt * 8;
            prow[cb + P0]                = tf32r(sacc[nt][0]);
            prow[cb + P1]                = tf32r(sacc[nt][1]);
            prow[8 * FA_SROW + cb + P0]  = tf32r(sacc[nt][2]);
            prow[8 * FA_SROW + cb + P1]  = tf32r(sacc[nt][3]);
        }

        if (it + 1 < 16) cp_wait<1>(); else cp_wait<0>();
        __syncthreads();

        // ---- O += P @ V (both s-permuted; LDS.64 A- and B-frags) ----
        #pragma unroll
        for (int kk = 0; kk < 16; kk++) {
            const int colk2 = kk * 8 + 2 * qd;
            float2 p0 = *(const float2*)(prow + colk2);
            float2 p1 = *(const float2*)(prow + 8 * FA_SROW + colk2);
            uint32_t pa[4] = { __float_as_uint(p0.x), __float_as_uint(p1.x),
                               __float_as_uint(p0.y), __float_as_uint(p1.y) };
            #pragma unroll
            for (int nt = 0; nt < 16; nt++) {
                float2 b0 = *(const float2*)(sV + (nt * 8 + group) * FA_SROW + colk2);
                uint32_t bf[2] = { __float_as_uint(b0.x), __float_as_uint(b0.y) };
                mma_tf32(oacc[nt], pa, bf);
            }
        }
        __syncthreads();
        if (it + 1 < 16) {
            const float* Vn = Vg + (it + 1) * 128;
            #pragma unroll
            for (int i = 0; i < 16; i++) {
                int idx = i * 256 + tid;
                int r = idx >> 5, c = (idx & 31) * 4;
                cp16(uV + (uint32_t)(r * FA_SROW + c) * 4, Vn + (size_t)r * S_LEN + c);
            }
            cp_commit();
        }
    }

    // finalize: att written K-PERMUTED (within 8-groups) for the O-proj GEMM
    float inv0 = 1.0f / l0, inv1 = 1.0f / l1;
    int ra = q0 + wid * 16 + group;
    float* outa = att + (size_t)(b * S_LEN + ra) * D_MODEL + h * HDIM;
    float* outb = outa + 8 * (size_t)D_MODEL;
    #pragma unroll
    for (int nt = 0; nt < 16; nt++) {
        int cb = nt * 8;
        outa[cb + P0] = tf32r(oacc[nt][0] * inv0);
        outa[cb + P1] = tf32r(oacc[nt][1] * inv0);
        outb[cb + P0] = tf32r(oacc[nt][2] * inv1);
        outb[cb + P1] = tf32r(oacc[nt][3] * inv1);
    }
}

// ---------------------------------------------------------------------------
// Launch
// ---------------------------------------------------------------------------
extern "C" void kernel_launch(void* const* d_in, const int* in_sizes, int n_in,
                              void* d_out, int out_size) {
    const float* x  = (const float*)d_in[0];
    const float* Wq = (const float*)d_in[1];
    const float* bq = (const float*)d_in[2];
    const float* Wk = (const float*)d_in[3];
    const float* bk = (const float*)d_in[4];
    const float* Wv = (const float*)d_in[5];
    const float* bv = (const float*)d_in[6];
    const float* Wo = (const float*)d_in[7];
    const float* bo = (const float*)d_in[8];
    float* out = (float*)d_out;

    float *q, *k, *vt, *att, *wt;
    cudaGetSymbolAddress((void**)&q,   g_q);
    cudaGetSymbolAddress((void**)&k,   g_k);
    cudaGetSymbolAddress((void**)&vt,  g_vt);
    cudaGetSymbolAddress((void**)&att, g_att);
    cudaGetSymbolAddress((void**)&wt,  g_wt);
    float* wt0 = wt;
    float* wt1 = wt + (size_t)D_MODEL * D_MODEL;
    float* wt2 = wt + 2 * (size_t)D_MODEL * D_MODEL;
    float* wt3 = wt + 3 * (size_t)D_MODEL * D_MODEL;
    float* xr = att;   // att buffer reused as tf32-rounded, K-permuted x

    cudaFuncSetAttribute((const void*)tc_gemm_qkv,
                         cudaFuncAttributeMaxDynamicSharedMemorySize, GEMM_SMEM_SZ);
    cudaFuncSetAttribute((const void*)tc_gemm_o,
                         cudaFuncAttributeMaxDynamicSharedMemorySize, GEMM_SMEM_SZ);
    cudaFuncSetAttribute((const void*)fa_kernel,
                         cudaFuncAttributeMaxDynamicSharedMemorySize, FA_SMEM_SZ);

    // 0. preprocessing: all W^T (permuted); x rounded+permuted; RoPE tables
    dim3 tb(32, 8);
    dim3 tg4(D_MODEL / 32, D_MODEL / 32, 4);
    transpose4_kernel<<<tg4, tb>>>(Wq, Wk, Wv, Wo, wt);
    int nx = NB * S_LEN * D_MODEL;
    round_copy_kernel<<<(nx + 255) / 256, 256>>>(x, xr, nx);
    rope_tables_kernel<<<(S_LEN * HALF_HD + 255) / 256, 256>>>();

    // 1. QKV projections (z=0:Q+RoPE d-perm, 1:K+RoPE d-perm, 2:V^T s-perm)
    dim3 gQKV(D_MODEL / 128, (NB * S_LEN) / 128, 3);    // (16, 32, 3)
    tc_gemm_qkv<<<gQKV, 128, GEMM_SMEM_SZ>>>(xr, wt0, wt1, wt2, bq, bk, bv,
                                             q, k, vt);

    // 2. fused attention -> att (K-permuted; overwrites xr)
    dim3 gFA(S_LEN / 128, BH);                          // (16, 32)
    fa_kernel<<<gFA, 256, FA_SMEM_SZ>>>(q, k, vt, att);

    // 3. out = att @ Wo + bo
    dim3 gO(D_MODEL / 128, (NB * S_LEN) / 128);         // (16, 32)
    tc_gemm_o<<<gO, 128, GEMM_SMEM_SZ>>>(att, wt3, bo, out);
}

// round 13
// speedup vs baseline: 1.4401x; 1.4401x over previous
#include <cuda_runtime.h>
#include <math.h>
#include <cstdint>

// Problem constants
#define S_LEN 2048
#define D_MODEL 2048
#define NB 2
#define NH 16
#define HDIM 128
#define BH (NB*NH)
#define HALF_HD 64

// ---------------------------------------------------------------------------
// Scratch
// ---------------------------------------------------------------------------
__device__ float g_q  [NB*S_LEN*D_MODEL];
__device__ float g_k  [NB*S_LEN*D_MODEL];
__device__ float g_vt [BH*HDIM*S_LEN];          // V^T per (b,h): [128][2048]
__device__ float g_att[NB*S_LEN*D_MODEL];       // doubles as tf32-rounded x (K-PERMUTED)
__device__ float g_wt [4*D_MODEL*D_MODEL];      // W^T (tf32-rounded, K-PERMUTED)
__device__ float g_cos[S_LEN*HALF_HD];
__device__ float g_sin[S_LEN*HALF_HD];

// ---------------------------------------------------------------------------
// Helpers
// ---------------------------------------------------------------------------
__device__ __forceinline__ float tf32r(float x) {
    uint32_t u = __float_as_uint(x);
    asm("cvt.rna.tf32.f32 %0, %1;" : "=r"(u) : "r"(u));
    return __uint_as_float(u);
}

// K-dim permutation within each 8-group: col j -> (j<4 ? 2j : 2j-7).
// Makes fragment pairs (qd, qd+4) adjacent for LDS.64.
__device__ __forceinline__ int kperm(int j) {
    return (j < 4) ? (2 * j) : (2 * j - 7);
}

__device__ __forceinline__ uint32_t smem_u32(const void* p) {
    uint32_t a;
    asm("{ .reg .u64 t; cvta.to.shared.u64 t, %1; cvt.u32.u64 %0, t; }"
        : "=r"(a) : "l"(p));
    return a;
}

__device__ __forceinline__ void cp16(uint32_t dst, const float* src) {
    asm volatile("cp.async.cg.shared.global [%0], [%1], 16;" :: "r"(dst), "l"(src));
}
__device__ __forceinline__ void cp_commit() {
    asm volatile("cp.async.commit_group;");
}
template<int N>
__device__ __forceinline__ void cp_wait() {
    asm volatile("cp.async.wait_group %0;" :: "n"(N));
}

__device__ __forceinline__ void mma_tf32(float* c, const uint32_t* a, const uint32_t* b) {
    asm volatile(
        "mma.sync.aligned.m16n8k8.row.col.f32.tf32.tf32.f32 "
        "{%0,%1,%2,%3}, {%4,%5,%6,%7}, {%8,%9}, {%0,%1,%2,%3};"
        : "+f"(c[0]), "+f"(c[1]), "+f"(c[2]), "+f"(c[3])
        : "r"(a[0]), "r"(a[1]), "r"(a[2]), "r"(a[3]), "r"(b[0]), "r"(b[1]));
}

// ---------------------------------------------------------------------------
// RoPE tables
// ---------------------------------------------------------------------------
__global__ void rope_tables_kernel() {
    int idx = blockIdx.x * blockDim.x + threadIdx.x;
    if (idx >= S_LEN * HALF_HD) return;
    int s = idx / HALF_HD;
    int i = idx % HALF_HD;
    float inv = expf(-((float)(2 * i) / (float)HDIM) * logf(10000.0f));
    float f = (float)s * inv;
    g_cos[idx] = cosf(f);
    g_sin[idx] = sinf(f);
}

// ---------------------------------------------------------------------------
// x -> tf32-rounded, K-permuted copy
// ---------------------------------------------------------------------------
__global__ void round_copy_kernel(const float* __restrict__ in, float* __restrict__ out, int n) {
    int i = blockIdx.x * blockDim.x + threadIdx.x;
    if (i >= n) return;
    int c = i & (D_MODEL - 1);
    int pc = (c & ~7) | kperm(c & 7);
    out[(i & ~(D_MODEL - 1)) | pc] = tf32r(in[i]);
}

// ---------------------------------------------------------------------------
// 4x 2048x2048 transpose, tf32-rounded, K-permuted output (z selects W)
// ---------------------------------------------------------------------------
__global__ void transpose4_kernel(const float* __restrict__ Wq, const float* __restrict__ Wk,
                                  const float* __restrict__ Wv, const float* __restrict__ Wo,
                                  float* __restrict__ wt) {
    __shared__ float t[32][33];
    const float* in = (blockIdx.z == 0) ? Wq : (blockIdx.z == 1) ? Wk
                     : (blockIdx.z == 2) ? Wv : Wo;
    float* out = wt + (size_t)blockIdx.z * D_MODEL * D_MODEL;
    int x = blockIdx.x * 32 + threadIdx.x;
    int y = blockIdx.y * 32 + threadIdx.y;
    #pragma unroll
    for (int j = 0; j < 32; j += 8)
        t[threadIdx.y + j][threadIdx.x] = tf32r(in[(size_t)(y + j) * D_MODEL + x]);
    __syncthreads();
    x = blockIdx.y * 32 + threadIdx.x;
    y = blockIdx.x * 32 + threadIdx.y;
    int px = (x & ~7) | kperm(x & 7);     // permute K-dim (out column)
    #pragma unroll
    for (int j = 0; j < 32; j += 8)
        out[(size_t)(y + j) * D_MODEL + px] = t[threadIdx.x][threadIdx.y + j];
}

// ---------------------------------------------------------------------------
// Shared GEMM mainloop: 128x128 CTA tile, BK=32, K=2048, 256 threads (8 warps),
// warp tile 64x32 (2x4 warp grid). 2-stage cp.async ping-pong. Operands
// K-PERMUTED; SROW=40 -> LDS.64 fragment loads conflict-free (bank-pair =
// 4*(group+kk)+qd mod 16, bijective per 16-lane phase).
// Result staged into sbase as Cs[128][CSTR].
// ---------------------------------------------------------------------------
#define SROW 40
#define TILE_F (128*SROW)                  // 5120 floats = 20480 B
#define GEMM_SMEM_SZ (2*2*TILE_F*4)        // 81920 B
#define CSTR 132

__device__ __forceinline__ void gemm_128x128(
    const float* __restrict__ Ag, const float* __restrict__ Bg,
    float* sbase, uint32_t s_u32, int tid)
{
    const int wid = tid >> 5;
    const int lane = tid & 31;
    const int group = lane >> 2;
    const int qd = lane & 3;
    const int wm = (wid >> 2) * 64;     // 0 or 64
    const int wn = (wid & 3) * 32;      // 0,32,64,96
    const int lr = tid >> 3;            // 0..31
    const int lc4 = (tid & 7) * 4;

    float acc[4][4][4];
    #pragma unroll
    for (int mt = 0; mt < 4; mt++)
        #pragma unroll
        for (int nt = 0; nt < 4; nt++)
            #pragma unroll
            for (int i = 0; i < 4; i++) acc[mt][nt][i] = 0.0f;

    // prologue: chunk 0 into stage 0 (4 float4 per thread per tile)
    {
        uint32_t sa = s_u32;
        uint32_t sb = s_u32 + TILE_F * 4;
        #pragma unroll
        for (int i = 0; i < 4; i++) {
            int r = i * 32 + lr;
            uint32_t so = (uint32_t)(r * SROW + lc4) * 4;
            cp16(sa + so, Ag + (size_t)r * D_MODEL + lc4);
            cp16(sb + so, Bg + (size_t)r * D_MODEL + lc4);
        }
        cp_commit();
    }

    for (int ch = 0; ch < 64; ch++) {
        const int st = ch & 1;
        if (ch + 1 < 64) {
            const int k0 = (ch + 1) << 5;
            uint32_t sa = s_u32 + (uint32_t)((ch + 1) & 1) * (2 * TILE_F * 4);
            uint32_t sb = sa + TILE_F * 4;
            #pragma unroll
            for (int i = 0; i < 4; i++) {
                int r = i * 32 + lr;
                uint32_t so = (uint32_t)(r * SROW + lc4) * 4;
                cp16(sa + so, Ag + (size_t)r * D_MODEL + k0 + lc4);
                cp16(sb + so, Bg + (size_t)r * D_MODEL + k0 + lc4);
            }
            cp_commit();
            cp_wait<1>();
        } else {
            cp_wait<0>();
        }
        __syncthreads();

        const float* As = sbase + st * 2 * TILE_F;
        const float* Bs = As + TILE_F;

        #pragma unroll
        for (int kk = 0; kk < 4; kk++) {
            // permuted layout: float2 at (kk*8 + 2qd) = original cols (qd, qd+4)
            const int colk2 = kk * 8 + 2 * qd;
            uint32_t af[4][4], bf[4][2];
            #pragma unroll
            for (int mt = 0; mt < 4; mt++) {
                int r0 = wm + mt * 16 + group;
                float2 a0 = *(const float2*)(As + r0 * SROW + colk2);
                float2 a1 = *(const float2*)(As + (r0 + 8) * SROW + colk2);
                af[mt][0] = __float_as_uint(a0.x);
                af[mt][1] = __float_as_uint(a1.x);
                af[mt][2] = __float_as_uint(a0.y);
                af[mt][3] = __float_as_uint(a1.y);
            }
            #pragma unroll
            for (int nt = 0; nt < 4; nt++) {
                int bn = wn + nt * 8 + group;
                float2 b0 = *(const float2*)(Bs + bn * SROW + colk2);
                bf[nt][0] = __float_as_uint(b0.x);
                bf[nt][1] = __float_as_uint(b0.y);
            }
            #pragma unroll
            for (int mt = 0; mt < 4; mt++)
                #pragma unroll
                for (int nt = 0; nt < 4; nt++)
                    mma_tf32(acc[mt][nt], af[mt], bf[nt]);
        }
        __syncthreads();
    }

    // stage C tile in smem
    float* Cs = sbase;
    #pragma unroll
    for (int mt = 0; mt < 4; mt++) {
        int r0 = wm + mt * 16 + group;
        #pragma unroll
        for (int nt = 0; nt < 4; nt++) {
            int cb = wn + nt * 8 + 2 * qd;
            Cs[r0 * CSTR + cb]           = acc[mt][nt][0];
            Cs[r0 * CSTR + cb + 1]       = acc[mt][nt][1];
            Cs[(r0 + 8) * CSTR + cb]     = acc[mt][nt][2];
            Cs[(r0 + 8) * CSTR + cb + 1] = acc[mt][nt][3];
        }
    }
    __syncthreads();
}

// ---------------------------------------------------------------------------
// QKV combined projection: grid (16, 32, 3), 256 threads. z=0: Q (RoPE),
// z=1: K (RoPE), z=2: V (transposed write). Outputs tf32-rounded, STANDARD
// layout (FA input) — identical addressing to R11.
// ---------------------------------------------------------------------------
__global__ void __launch_bounds__(256, 2)
tc_gemm_qkv(const float* __restrict__ A,
            const float* __restrict__ W0, const float* __restrict__ W1,
            const float* __restrict__ W2,
            const float* __restrict__ b0, const float* __restrict__ b1,
            const float* __restrict__ b2,
            float* __restrict__ Cq, float* __restrict__ Ck, float* __restrict__ Cv)
{
    extern __shared__ char smem_raw[];
    float* sbase = (float*)smem_raw;
    const uint32_t s_u32 = smem_u32(smem_raw);
    const int tid = threadIdx.x;
    const int z = blockIdx.z;
    const int m0 = blockIdx.y * 128;
    const int n0 = blockIdx.x * 128;

    const float* W = (z == 0) ? W0 : (z == 1) ? W1 : W2;
    const float* bias = (z == 0) ? b0 : (z == 1) ? b1 : b2;

    gemm_128x128(A + (size_t)m0 * D_MODEL, W + (size_t)n0 * D_MODEL,
                 sbase, s_u32, tid);
    const float* Cs = sbase;

    if (z < 2) {
        // RoPE epilogue into q or k: [b,s,2048] layout, pair (ci, ci+64)
        float* C = (z == 0) ? Cq : Ck;
        #pragma unroll
        for (int i = 0; i < 32; i++) {
            int flat = i * 256 + tid;
            int row = flat >> 6;
            int ci = flat & 63;
            float v1 = Cs[row * CSTR + ci]      + __ldg(bias + n0 + ci);
            float v2 = Cs[row * CSTR + ci + 64] + __ldg(bias + n0 + ci + 64);
            int s = (m0 + row) & (S_LEN - 1);
            float cv = g_cos[s * HALF_HD + ci];
            float sv = g_sin[s * HALF_HD + ci];
            float o1 = v1 * cv - v2 * sv;
            float o2 = v1 * sv + v2 * cv;
            float* dst = C + (size_t)(m0 + row) * D_MODEL + n0 + ci;
            dst[0]  = tf32r(o1);
            dst[64] = tf32r(o2);
        }
    } else {
        // V^T epilogue: vt[((b*16+h)*128 + d)*S_LEN + s]
        const int h = n0 >> 7;
        #pragma unroll
        for (int i = 0; i < 64; i++) {
            int flat = i * 256 + tid;
            int sl = flat & 127;
            int d = flat >> 7;
            float v = Cs[sl * CSTR + d] + __ldg(bias + n0 + d);
            int b = (m0 + sl) >> 11;
            int s = (m0 + sl) & (S_LEN - 1);
            Cv[((size_t)(b * NH + h) * HDIM + d) * S_LEN + s] = tf32r(v);
        }
    }
}

// ---------------------------------------------------------------------------
// Output projection: plain bias epilogue, full fp32 standard-layout output.
// ---------------------------------------------------------------------------
__global__ void __launch_bounds__(256, 2)
tc_gemm_o(const float* __restrict__ A, const float* __restrict__ W,
          const float* __restrict__ bias, float* __restrict__ C)
{
    extern __shared__ char smem_raw[];
    float* sbase = (float*)smem_raw;
    const uint32_t s_u32 = smem_u32(smem_raw);
    const int tid = threadIdx.x;
    const int m0 = blockIdx.y * 128;
    const int n0 = blockIdx.x * 128;

    gemm_128x128(A + (size_t)m0 * D_MODEL, W + (size_t)n0 * D_MODEL,
                 sbase, s_u32, tid);
    const float* Cs = sbase;

    const int col4 = (tid & 31) * 4;
    float bv[4];
    bv[0] = __ldg(bias + n0 + col4);
    bv[1] = __ldg(bias + n0 + col4 + 1);
    bv[2] = __ldg(bias + n0 + col4 + 2);
    bv[3] = __ldg(bias + n0 + col4 + 3);
    #pragma unroll
    for (int i = 0; i < 16; i++) {
        int row = (tid >> 5) + i * 8;
        const float* src = Cs + row * CSTR + col4;
        float4 v;
        v.x = src[0] + bv[0];
        v.y = src[1] + bv[1];
        v.z = src[2] + bv[2];
        v.w = src[3] + bv[3];
        *(float4*)(C + (size_t)(m0 + row) * D_MODEL + n0 + col4) = v;
    }
}

// ---------------------------------------------------------------------------
// Flash attention: per (q-tile 128, bh). 256 threads, 8 warps x (16 rows,
// 128 cols). IDENTICAL to R11 (best passing version).
// ---------------------------------------------------------------------------
#define FA_SROW 132
#define FA_TILE (128*FA_SROW)
#define FA_SMEM_SZ (3*FA_TILE*4)      // 202752 bytes

__global__ void __launch_bounds__(256, 1)
fa_kernel(const float* __restrict__ q, const float* __restrict__ k,
          const float* __restrict__ vt, float* __restrict__ att)
{
    extern __shared__ float sm[];
    float* sQP = sm;
    float* sK  = sm + FA_TILE;
    float* sV  = sm + 2 * FA_TILE;
    const uint32_t uQP = smem_u32(sQP);
    const uint32_t uK  = smem_u32(sK);
    const uint32_t uV  = smem_u32(sV);

    const int tid = threadIdx.x;
    const int wid = tid >> 5;
    const int lane = tid & 31;
    const int group = lane >> 2;
    const int qd = lane & 3;
    const int bh = blockIdx.y;
    const int b = bh >> 4, h = bh & 15;
    const int q0 = blockIdx.x * 128;

    const float* Qg = q + ((size_t)(b * S_LEN + q0)) * D_MODEL + h * HDIM;
    const float* Kg = k + ((size_t)b * S_LEN) * D_MODEL + h * HDIM;
    const float* Vg = vt + (size_t)bh * HDIM * S_LEN;

    #pragma unroll
    for (int i = 0; i < 16; i++) {
        int idx = i * 256 + tid;
        int r = idx >> 5, c = (idx & 31) * 4;
        cp16(uQP + (uint32_t)(r * FA_SROW + c) * 4, Qg + (size_t)r * D_MODEL + c);
    }
    cp_commit();
    #pragma unroll
    for (int i = 0; i < 16; i++) {
        int idx = i * 256 + tid;
        int r = idx >> 5, c = (idx & 31) * 4;
        cp16(uK + (uint32_t)(r * FA_SROW + c) * 4, Kg + (size_t)r * D_MODEL + c);
    }
    cp_commit();
    cp_wait<1>();
    __syncthreads();

    uint32_t qa[16][4];
    {
        const float* base = sQP + (wid * 16 + group) * FA_SROW;
        #pragma unroll
        for (int kk = 0; kk < 16; kk++) {
            qa[kk][0] = __float_as_uint(base[kk * 8 + qd]);
            qa[kk][1] = __float_as_uint(base[8 * FA_SROW + kk * 8 + qd]);
            qa[kk][2] = __float_as_uint(base[kk * 8 + qd + 4]);
            qa[kk][3] = __float_as_uint(base[8 * FA_SROW + kk * 8 + qd + 4]);
        }
    }
    __syncthreads();
    #pragma unroll
    for (int i = 0; i < 16; i++) {
        int idx = i * 256 + tid;
        int r = idx >> 5, c = (idx & 31) * 4;
        cp16(uV + (uint32_t)(r * FA_SROW + c) * 4, Vg + (size_t)r * S_LEN + c);
    }
    cp_commit();

    const float alpha = 0.08838834764831843f;
    float m0 = -1e30f, m1 = -1e30f, l0 = 0.0f, l1 = 0.0f;
    float oacc[16][4];
    #pragma unroll
    for (int nt = 0; nt < 16; nt++)
        #pragma unroll
        for (int i = 0; i < 4; i++) oacc[nt][i] = 0.0f;

    float* prow = sQP + (wid * 16 + group) * FA_SROW;

    for (int it = 0; it < 16; it++) {
        cp_wait<1>();
        __syncthreads();

        float sacc[16][4];
        #pragma unroll
        for (int nt = 0; nt < 16; nt++)
            #pragma unroll
            for (int i = 0; i < 4; i++) sacc[nt][i] = 0.0f;

        #pragma unroll
        for (int kk = 0; kk < 16; kk++) {
            const int colk = kk * 8 + qd;
            #pragma unroll
            for (int nt = 0; nt < 16; nt++) {
                uint32_t bf[2];
                const float* bp = sK + (nt * 8 + group) * FA_SROW + colk;
                bf[0] = __float_as_uint(bp[0]);
                bf[1] = __float_as_uint(bp[4]);
                mma_tf32(sacc[nt], qa[kk], bf);
            }
        }
        __syncthreads();
        if (it + 1 < 16) {
            const float* Kn = Kg + (size_t)(it + 1) * 128 * D_MODEL;
            #pragma unroll
            for (int i = 0; i < 16; i++) {
                int idx = i * 256 + tid;
                int r = idx >> 5, c = (idx & 31) * 4;
                cp16(uK + (uint32_t)(r * FA_SROW + c) * 4, Kn + (size_t)r * D_MODEL + c);
            }
            cp_commit();
        }

        float mxa = -1e30f, mxb = -1e30f;
        #pragma unroll
        for (int nt = 0; nt < 16; nt++) {
            sacc[nt][0] *= alpha; sacc[nt][1] *= alpha;
            sacc[nt][2] *= alpha; sacc[nt][3] *= alpha;
            mxa = fmaxf(mxa, fmaxf(sacc[nt][0], sacc[nt][1]));
            mxb = fmaxf(mxb, fmaxf(sacc[nt][2], sacc[nt][3]));
        }
        mxa = fmaxf(mxa, __shfl_xor_sync(0xFFFFFFFF, mxa, 1));
        mxa = fmaxf(mxa, __shfl_xor_sync(0xFFFFFFFF, mxa, 2));
        mxb = fmaxf(mxb, __shfl_xor_sync(0xFFFFFFFF, mxb, 1));
        mxb = fmaxf(mxb, __shfl_xor_sync(0xFFFFFFFF, mxb, 2));
        float na = fmaxf(m0, mxa), nb = fmaxf(m1, mxb);
        float fa_ = __expf(m0 - na), fb_ = __expf(m1 - nb);
        float psa = 0.0f, psb = 0.0f;
        #pragma unroll
        for (int nt = 0; nt < 16; nt++) {
            sacc[nt][0] = __expf(sacc[nt][0] - na);
            sacc[nt][1] = __expf(sacc[nt][1] - na);
            sacc[nt][2] = __expf(sacc[nt][2] - nb);
            sacc[nt][3] = __expf(sacc[nt][3] - nb);
            psa += sacc[nt][0] + sacc[nt][1];
            psb += sacc[nt][2] + sacc[nt][3];
        }
        psa += __shfl_xor_sync(0xFFFFFFFF, psa, 1);
        psa += __shfl_xor_sync(0xFFFFFFFF, psa, 2);
        psb += __shfl_xor_sync(0xFFFFFFFF, psb, 1);
        psb += __shfl_xor_sync(0xFFFFFFFF, psb, 2);
        l0 = l0 * fa_ + psa; l1 = l1 * fb_ + psb;
        m0 = na; m1 = nb;
        #pragma unroll
        for (int nt = 0; nt < 16; nt++) {
            oacc[nt][0] *= fa_; oacc[nt][1] *= fa_;
            oacc[nt][2] *= fb_; oacc[nt][3] *= fb_;
        }
        #pragma unroll
        for (int nt = 0; nt < 16; nt++) {
            int cb = nt * 8 + 2 * qd;
            *(float2*)(prow + cb) =
                make_float2(tf32r(sacc[nt][0]), tf32r(sacc[nt][1]));
            *(float2*)(prow + 8 * FA_SROW + cb) =
                make_float2(tf32r(sacc[nt][2]), tf32r(sacc[nt][3]));
        }

        if (it + 1 < 16) cp_wait<1>(); else cp_wait<0>();
        __syncthreads();

        #pragma unroll
        for (int kk = 0; kk < 16; kk++) {
            const int colk = kk * 8 + qd;
            uint32_t pa[4];
            pa[0] = __float_as_uint(prow[colk]);
            pa[1] = __float_as_uint(prow[8 * FA_SROW + colk]);
            pa[2] = __float_as_uint(prow[colk + 4]);
            pa[3] = __float_as_uint(prow[8 * FA_SROW + colk + 4]);
            #pragma unroll
            for (int nt = 0; nt < 16; nt++) {
                uint32_t bf[2];
                const float* bp = sV + (nt * 8 + group) * FA_SROW + colk;
                bf[0] = __float_as_uint(bp[0]);
                bf[1] = __float_as_uint(bp[4]);
                mma_tf32(oacc[nt], pa, bf);
            }
        }
        __syncthreads();
        if (it + 1 < 16) {
            const float* Vn = Vg + (it + 1) * 128;
            #pragma unroll
            for (int i = 0; i < 16; i++) {
                int idx = i * 256 + tid;
                int r = idx >> 5, c = (idx & 31) * 4;
                cp16(uV + (uint32_t)(r * FA_SROW + c) * 4, Vn + (size_t)r * S_LEN + c);
            }
            cp_commit();
        }
    }

    // finalize: att written K-PERMUTED (within 8-groups) for the O-proj GEMM
    float inv0 = 1.0f / l0, inv1 = 1.0f / l1;
    int ra = q0 + wid * 16 + group;
    float* outa = att + (size_t)(b * S_LEN + ra) * D_MODEL + h * HDIM;
    float* outb = outa + 8 * (size_t)D_MODEL;
    const int P0 = kperm(2 * qd);
    const int P1 = kperm(2 * qd + 1);
    #pragma unroll
    for (int nt = 0; nt < 16; nt++) {
        int cb = nt * 8;
        outa[cb + P0] = tf32r(oacc[nt][0] * inv0);
        outa[cb + P1] = tf32r(oacc[nt][1] * inv0);
        outb[cb + P0] = tf32r(oacc[nt][2] * inv1);
        outb[cb + P1] = tf32r(oacc[nt][3] * inv1);
    }
}

// ---------------------------------------------------------------------------
// Launch
// ---------------------------------------------------------------------------
extern "C" void kernel_launch(void* const* d_in, const int* in_sizes, int n_in,
                              void* d_out, int out_size) {
    const float* x  = (const float*)d_in[0];
    const float* Wq = (const float*)d_in[1];
    const float* bq = (const float*)d_in[2];
    const float* Wk = (const float*)d_in[3];
    const float* bk = (const float*)d_in[4];
    const float* Wv = (const float*)d_in[5];
    const float* bv = (const float*)d_in[6];
    const float* Wo = (const float*)d_in[7];
    const float* bo = (const float*)d_in[8];
    float* out = (float*)d_out;

    float *q, *k, *vt, *att, *wt;
    cudaGetSymbolAddress((void**)&q,   g_q);
    cudaGetSymbolAddress((void**)&k,   g_k);
    cudaGetSymbolAddress((void**)&vt,  g_vt);
    cudaGetSymbolAddress((void**)&att, g_att);
    cudaGetSymbolAddress((void**)&wt,  g_wt);
    float* wt0 = wt;
    float* wt1 = wt + (size_t)D_MODEL * D_MODEL;
    float* wt2 = wt + 2 * (size_t)D_MODEL * D_MODEL;
    float* wt3 = wt + 3 * (size_t)D_MODEL * D_MODEL;
    float* xr = att;   // att buffer reused as tf32-rounded, K-permuted x

    cudaFuncSetAttribute((const void*)tc_gemm_qkv,
                         cudaFuncAttributeMaxDynamicSharedMemorySize, GEMM_SMEM_SZ);
    cudaFuncSetAttribute((const void*)tc_gemm_o,
                         cudaFuncAttributeMaxDynamicSharedMemorySize, GEMM_SMEM_SZ);
    cudaFuncSetAttribute((const void*)fa_kernel,
                         cudaFuncAttributeMaxDynamicSharedMemorySize, FA_SMEM_SZ);

    // 0. preprocessing: all W^T (permuted); x rounded+permuted; RoPE tables
    dim3 tb(32, 8);
    dim3 tg4(D_MODEL / 32, D_MODEL / 32, 4);
    transpose4_kernel<<<tg4, tb>>>(Wq, Wk, Wv, Wo, wt);
    int nx = NB * S_LEN * D_MODEL;
    round_copy_kernel<<<(nx + 255) / 256, 256>>>(x, xr, nx);
    rope_tables_kernel<<<(S_LEN * HALF_HD + 255) / 256, 256>>>();

    // 1. QKV projections in one launch (z=0:Q+RoPE, 1:K+RoPE, 2:V^T)
    dim3 gQKV(D_MODEL / 128, (NB * S_LEN) / 128, 3);    // (16, 32, 3)
    tc_gemm_qkv<<<gQKV, 256, GEMM_SMEM_SZ>>>(xr, wt0, wt1, wt2, bq, bk, bv,
                                             q, k, vt);

    // 2. fused attention -> att (K-permuted; overwrites xr)
    dim3 gFA(S_LEN / 128, BH);                          // (16, 32)
    fa_kernel<<<gFA, 256, FA_SMEM_SZ>>>(q, k, vt, att);

    // 3. out = att @ Wo + bo
    dim3 gO(D_MODEL / 128, (NB * S_LEN) / 128);         // (16, 32)
    tc_gemm_o<<<gO, 256, GEMM_SMEM_SZ>>>(att, wt3, bo, out);
}

// round 15
// speedup vs baseline: 1.5649x; 1.0867x over previous
#include <cuda_runtime.h>
#include <math.h>
#include <cstdint>

// Problem constants
#define S_LEN 2048
#define D_MODEL 2048
#define NB 2
#define NH 16
#define HDIM 128
#define BH (NB*NH)
#define HALF_HD 64

// ---------------------------------------------------------------------------
// Scratch
// ---------------------------------------------------------------------------
__device__ float g_q  [NB*S_LEN*D_MODEL];
__device__ float g_k  [NB*S_LEN*D_MODEL];
__device__ float g_vt [BH*HDIM*S_LEN];          // V^T per (b,h): [128][2048]
__device__ float g_att[NB*S_LEN*D_MODEL];       // doubles as tf32-rounded x (K-PERMUTED)
__device__ float g_wt [4*D_MODEL*D_MODEL];      // W^T (tf32-rounded, K-PERMUTED)
__device__ float g_cos[S_LEN*HALF_HD];
__device__ float g_sin[S_LEN*HALF_HD];

// ---------------------------------------------------------------------------
// Helpers
// ---------------------------------------------------------------------------
__device__ __forceinline__ float tf32r(float x) {
    uint32_t u = __float_as_uint(x);
    asm("cvt.rna.tf32.f32 %0, %1;" : "=r"(u) : "r"(u));
    return __uint_as_float(u);
}

// K-dim permutation within each 8-group: col j -> (j<4 ? 2j : 2j-7).
__device__ __forceinline__ int kperm(int j) {
    return (j < 4) ? (2 * j) : (2 * j - 7);
}

__device__ __forceinline__ uint32_t smem_u32(const void* p) {
    uint32_t a;
    asm("{ .reg .u64 t; cvta.to.shared.u64 t, %1; cvt.u32.u64 %0, t; }"
        : "=r"(a) : "l"(p));
    return a;
}

__device__ __forceinline__ void cp16(uint32_t dst, const void* src) {
    asm volatile("cp.async.cg.shared.global [%0], [%1], 16;" :: "r"(dst), "l"(src));
}
__device__ __forceinline__ void cp_commit() {
    asm volatile("cp.async.commit_group;");
}
template<int N>
__device__ __forceinline__ void cp_wait() {
    asm volatile("cp.async.wait_group %0;" :: "n"(N));
}

__device__ __forceinline__ void mma_tf32(float* c, const uint32_t* a, const uint32_t* b) {
    asm volatile(
        "mma.sync.aligned.m16n8k8.row.col.f32.tf32.tf32.f32 "
        "{%0,%1,%2,%3}, {%4,%5,%6,%7}, {%8,%9}, {%0,%1,%2,%3};"
        : "+f"(c[0]), "+f"(c[1]), "+f"(c[2]), "+f"(c[3])
        : "r"(a[0]), "r"(a[1]), "r"(a[2]), "r"(a[3]), "r"(b[0]), "r"(b[1]));
}

// ---------------------------------------------------------------------------
// RoPE tables
// ---------------------------------------------------------------------------
__global__ void rope_tables_kernel() {
    int idx = blockIdx.x * blockDim.x + threadIdx.x;
    if (idx >= S_LEN * HALF_HD) return;
    int s = idx / HALF_HD;
    int i = idx % HALF_HD;
    float inv = expf(-((float)(2 * i) / (float)HDIM) * logf(10000.0f));
    float f = (float)s * inv;
    g_cos[idx] = cosf(f);
    g_sin[idx] = sinf(f);
}

// ---------------------------------------------------------------------------
// x -> tf32-rounded, K-permuted copy
// ---------------------------------------------------------------------------
__global__ void round_copy_kernel(const float* __restrict__ in, float* __restrict__ out, int n) {
    int i = blockIdx.x * blockDim.x + threadIdx.x;
    if (i >= n) return;
    int c = i & (D_MODEL - 1);
    int pc = (c & ~7) | kperm(c & 7);
    out[(i & ~(D_MODEL - 1)) | pc] = tf32r(in[i]);
}

// ---------------------------------------------------------------------------
// 4x 2048x2048 transpose, tf32-rounded, K-permuted output (z selects W)
// ---------------------------------------------------------------------------
__global__ void transpose4_kernel(const float* __restrict__ Wq, const float* __restrict__ Wk,
                                  const float* __restrict__ Wv, const float* __restrict__ Wo,
                                  float* __restrict__ wt) {
    __shared__ float t[32][33];
    const float* in = (blockIdx.z == 0) ? Wq : (blockIdx.z == 1) ? Wk
                     : (blockIdx.z == 2) ? Wv : Wo;
    float* out = wt + (size_t)blockIdx.z * D_MODEL * D_MODEL;
    int x = blockIdx.x * 32 + threadIdx.x;
    int y = blockIdx.y * 32 + threadIdx.y;
    #pragma unroll
    for (int j = 0; j < 32; j += 8)
        t[threadIdx.y + j][threadIdx.x] = tf32r(in[(size_t)(y + j) * D_MODEL + x]);
    __syncthreads();
    x = blockIdx.y * 32 + threadIdx.x;
    y = blockIdx.x * 32 + threadIdx.y;
    int px = (x & ~7) | kperm(x & 7);     // permute K-dim (out column)
    #pragma unroll
    for (int j = 0; j < 32; j += 8)
        out[(size_t)(y + j) * D_MODEL + px] = t[threadIdx.x][threadIdx.y + j];
}

// ---------------------------------------------------------------------------
// Shared GEMM mainloop (EXACT R11): 128x128 tile, BK=32, 128 threads (4 warps),
// warp tile 64x64. 2-stage cp.async. K-PERMUTED operands; SROW=40 -> LDS.64
// conflict-free. Result staged as Cs[128][CSTR].
// ---------------------------------------------------------------------------
#define SROW 40
#define TILE_F (128*SROW)
#define GEMM_SMEM_SZ (2*2*TILE_F*4)        // 81920 B
#define CSTR 132

__device__ __forceinline__ void gemm_128x128(
    const float* __restrict__ Ag, const float* __restrict__ Bg,
    float* sbase, uint32_t s_u32, int tid)
{
    const int wid = tid >> 5;
    const int lane = tid & 31;
    const int group = lane >> 2;
    const int qd = lane & 3;
    const int wm = (wid >> 1) * 64;
    const int wn = (wid & 1) * 64;
    const int lr = tid >> 3;
    const int lc4 = (tid & 7) * 4;

    float acc[4][8][4];
    #pragma unroll
    for (int mt = 0; mt < 4; mt++)
        #pragma unroll
        for (int nt = 0; nt < 8; nt++)
            #pragma unroll
            for (int i = 0; i < 4; i++) acc[mt][nt][i] = 0.0f;

    {
        uint32_t sa = s_u32;
        uint32_t sb = s_u32 + TILE_F * 4;
        #pragma unroll
        for (int i = 0; i < 8; i++) {
            int r = i * 16 + lr;
            uint32_t so = (uint32_t)(r * SROW + lc4) * 4;
            cp16(sa + so, Ag + (size_t)r * D_MODEL + lc4);
            cp16(sb + so, Bg + (size_t)r * D_MODEL + lc4);
        }
        cp_commit();
    }

    for (int ch = 0; ch < 64; ch++) {
        const int st = ch & 1;
        if (ch + 1 < 64) {
            const int k0 = (ch + 1) << 5;
            uint32_t sa = s_u32 + (uint32_t)((ch + 1) & 1) * (2 * TILE_F * 4);
            uint32_t sb = sa + TILE_F * 4;
            #pragma unroll
            for (int i = 0; i < 8; i++) {
                int r = i * 16 + lr;
                uint32_t so = (uint32_t)(r * SROW + lc4) * 4;
                cp16(sa + so, Ag + (size_t)r * D_MODEL + k0 + lc4);
                cp16(sb + so, Bg + (size_t)r * D_MODEL + k0 + lc4);
            }
            cp_commit();
            cp_wait<1>();
        } else {
            cp_wait<0>();
        }
        __syncthreads();

        const float* As = sbase + st * 2 * TILE_F;
        const float* Bs = As + TILE_F;

        #pragma unroll
        for (int kk = 0; kk < 4; kk++) {
            const int colk2 = kk * 8 + 2 * qd;
            uint32_t af[4][4], bf[8][2];
            #pragma unroll
            for (int mt = 0; mt < 4; mt++) {
                int r0 = wm + mt * 16 + group;
                float2 a0 = *(const float2*)(As + r0 * SROW + colk2);
                float2 a1 = *(const float2*)(As + (r0 + 8) * SROW + colk2);
                af[mt][0] = __float_as_uint(a0.x);
                af[mt][1] = __float_as_uint(a1.x);
                af[mt][2] = __float_as_uint(a0.y);
                af[mt][3] = __float_as_uint(a1.y);
            }
            #pragma unroll
            for (int nt = 0; nt < 8; nt++) {
                int bn = wn + nt * 8 + group;
                float2 b0 = *(const float2*)(Bs + bn * SROW + colk2);
                bf[nt][0] = __float_as_uint(b0.x);
                bf[nt][1] = __float_as_uint(b0.y);
            }
            #pragma unroll
            for (int mt = 0; mt < 4; mt++)
                #pragma unroll
                for (int nt = 0; nt < 8; nt++)
                    mma_tf32(acc[mt][nt], af[mt], bf[nt]);
        }
        __syncthreads();
    }

    float* Cs = sbase;
    #pragma unroll
    for (int mt = 0; mt < 4; mt++) {
        int r0 = wm + mt * 16 + group;
        #pragma unroll
        for (int nt = 0; nt < 8; nt++) {
            int cb = wn + nt * 8 + 2 * qd;
            Cs[r0 * CSTR + cb]           = acc[mt][nt][0];
            Cs[r0 * CSTR + cb + 1]       = acc[mt][nt][1];
            Cs[(r0 + 8) * CSTR + cb]     = acc[mt][nt][2];
            Cs[(r0 + 8) * CSTR + cb + 1] = acc[mt][nt][3];
        }
    }
    __syncthreads();
}

// ---------------------------------------------------------------------------
// QKV combined projection (EXACT R11): grid (16, 32, 3), 128 threads.
// z=0/1: Q/K with RoPE, standard fp32 layout. z=2: V^T standard.
// ---------------------------------------------------------------------------
__global__ void __launch_bounds__(128, 2)
tc_gemm_qkv(const float* __restrict__ A,
            const float* __restrict__ W0, const float* __restrict__ W1,
            const float* __restrict__ W2,
            const float* __restrict__ b0, const float* __restrict__ b1,
            const float* __restrict__ b2,
            float* __restrict__ Cq, float* __restrict__ Ck, float* __restrict__ Cv)
{
    extern __shared__ char smem_raw[];
    float* sbase = (float*)smem_raw;
    const uint32_t s_u32 = smem_u32(smem_raw);
    const int tid = threadIdx.x;
    const int z = blockIdx.z;
    const int m0 = blockIdx.y * 128;
    const int n0 = blockIdx.x * 128;

    const float* W = (z == 0) ? W0 : (z == 1) ? W1 : W2;
    const float* bias = (z == 0) ? b0 : (z == 1) ? b1 : b2;

    gemm_128x128(A + (size_t)m0 * D_MODEL, W + (size_t)n0 * D_MODEL,
                 sbase, s_u32, tid);
    const float* Cs = sbase;

    if (z < 2) {
        float* C = (z == 0) ? Cq : Ck;
        #pragma unroll
        for (int i = 0; i < 64; i++) {
            int flat = i * 128 + tid;
            int row = flat >> 6;
            int ci = flat & 63;
            float v1 = Cs[row * CSTR + ci]      + __ldg(bias + n0 + ci);
            float v2 = Cs[row * CSTR + ci + 64] + __ldg(bias + n0 + ci + 64);
            int s = (m0 + row) & (S_LEN - 1);
            float cv = g_cos[s * HALF_HD + ci];
            float sv = g_sin[s * HALF_HD + ci];
            float o1 = v1 * cv - v2 * sv;
            float o2 = v1 * sv + v2 * cv;
            float* dst = C + (size_t)(m0 + row) * D_MODEL + n0 + ci;
            dst[0]  = tf32r(o1);
            dst[64] = tf32r(o2);
        }
    } else {
        const int h = n0 >> 7;
        #pragma unroll
        for (int i = 0; i < 128; i++) {
            int flat = i * 128 + tid;
            int sl = flat & 127;
            int d = flat >> 7;
            float v = Cs[sl * CSTR + d] + __ldg(bias + n0 + d);
            int b = (m0 + sl) >> 11;
            int s = (m0 + sl) & (S_LEN - 1);
            Cv[((size_t)(b * NH + h) * HDIM + d) * S_LEN + s] = tf32r(v);
        }
    }
}

// ---------------------------------------------------------------------------
// Output projection (EXACT R11): plain bias epilogue, fp32 output.
// ---------------------------------------------------------------------------
__global__ void __launch_bounds__(128, 2)
tc_gemm_o(const float* __restrict__ A, const float* __restrict__ W,
          const float* __restrict__ bias, float* __restrict__ C)
{
    extern __shared__ char smem_raw[];
    float* sbase = (float*)smem_raw;
    const uint32_t s_u32 = smem_u32(smem_raw);
    const int tid = threadIdx.x;
    const int m0 = blockIdx.y * 128;
    const int n0 = blockIdx.x * 128;

    gemm_128x128(A + (size_t)m0 * D_MODEL, W + (size_t)n0 * D_MODEL,
                 sbase, s_u32, tid);
    const float* Cs = sbase;

    const int col4 = (tid & 31) * 4;
    float bv[4];
    bv[0] = __ldg(bias + n0 + col4);
    bv[1] = __ldg(bias + n0 + col4 + 1);
    bv[2] = __ldg(bias + n0 + col4 + 2);
    bv[3] = __ldg(bias + n0 + col4 + 3);
    #pragma unroll
    for (int i = 0; i < 32; i++) {
        int row = (tid >> 5) + i * 4;
        const float* src = Cs + row * CSTR + col4;
        float4 v;
        v.x = src[0] + bv[0];
        v.y = src[1] + bv[1];
        v.z = src[2] + bv[2];
        v.w = src[3] + bv[3];
        *(float4*)(C + (size_t)(m0 + row) * D_MODEL + n0 + col4) = v;
    }
}

// ---------------------------------------------------------------------------
// Flash attention, tf32, P-IN-REGISTERS.
// Slot pairing: k-slots (qd, qd+4) <- data cols (2qd, 2qd+1) on BOTH operands
// of every MMA. This makes the QK C-frag (cols 2qd,2qd+1) directly usable as
// the PV A-frag (reg order {c0,c2,c1,c3}) — no P smem staging — and makes all
// Q/K/V fragment loads LDS.64 on STANDARD-layout tiles.
// Pitch 136 floats: float2 stride 68 = 4 mod 16 -> conflict-free frag loads.
// Smem: K + V buffers only (Q staged transiently in V's buffer).
// att written fp32 K-PERMUTED (same as R11) for the O-proj GEMM.
// ---------------------------------------------------------------------------
#define FA_PITCH 136
#define FA_TILE (128*FA_PITCH)
#define FA_SMEM_SZ (2*FA_TILE*4)      // 139264 bytes

__global__ void __launch_bounds__(256, 1)
fa_kernel(const float* __restrict__ q, const float* __restrict__ k,
          const float* __restrict__ vt, float* __restrict__ att)
{
    extern __shared__ float sm[];
    float* sK = sm;
    float* sV = sm + FA_TILE;
    const uint32_t uK = smem_u32(sK);
    const uint32_t uV = smem_u32(sV);

    const int tid = threadIdx.x;
    const int wid = tid >> 5;
    const int lane = tid & 31;
    const int group = lane >> 2;
    const int qd = lane & 3;
    const int bh = blockIdx.y;
    const int b = bh >> 4, h = bh & 15;
    const int q0 = blockIdx.x * 128;

    const float* Qg = q + ((size_t)(b * S_LEN + q0)) * D_MODEL + h * HDIM;
    const float* Kg = k + ((size_t)b * S_LEN) * D_MODEL + h * HDIM;
    const float* Vg = vt + (size_t)bh * HDIM * S_LEN;

    // Q tile -> sV (transient), K(0) -> sK
    #pragma unroll
    for (int i = 0; i < 16; i++) {
        int idx = i * 256 + tid;
        int r = idx >> 5, c = (idx & 31) * 4;
        cp16(uV + (uint32_t)(r * FA_PITCH + c) * 4, Qg + (size_t)r * D_MODEL + c);
    }
    cp_commit();
    #pragma unroll
    for (int i = 0; i < 16; i++) {
        int idx = i * 256 + tid;
        int r = idx >> 5, c = (idx & 31) * 4;
        cp16(uK + (uint32_t)(r * FA_PITCH + c) * 4, Kg + (size_t)r * D_MODEL + c);
    }
    cp_commit();
    cp_wait<1>();            // Q complete (K0 may still be in flight)
    __syncthreads();

    const int rg = wid * 16 + group;

    // Q A-frags, slot-paired: qa[kk] covers head-dims (8kk+2qd, 8kk+2qd+1)
    uint32_t qa[16][4];
    {
        const float* b0p = sV + rg * FA_PITCH;
        const float* b1p = b0p + 8 * FA_PITCH;
        #pragma unroll
        for (int kk = 0; kk < 16; kk++) {
            float2 a0 = *(const float2*)(b0p + kk * 8 + 2 * qd);
            float2 a1 = *(const float2*)(b1p + kk * 8 + 2 * qd);
            qa[kk][0] = __float_as_uint(a0.x);
            qa[kk][1] = __float_as_uint(a1.x);
            qa[kk][2] = __float_as_uint(a0.y);
            qa[kk][3] = __float_as_uint(a1.y);
        }
    }
    __syncthreads();
    // V(0) -> sV (overwrites Q; all warps extracted qa above)
    #pragma unroll
    for (int i = 0; i < 16; i++) {
        int idx = i * 256 + tid;
        int r = idx >> 5, c = (idx & 31) * 4;
        cp16(uV + (uint32_t)(r * FA_PITCH + c) * 4, Vg + (size_t)r * S_LEN + c);
    }
    cp_commit();

    const float alpha = 0.08838834764831843f;
    float m0 = -1e30f, m1 = -1e30f, l0 = 0.0f, l1 = 0.0f;
    float oacc[16][4];
    #pragma unroll
    for (int nt = 0; nt < 16; nt++)
        #pragma unroll
        for (int i = 0; i < 4; i++) oacc[nt][i] = 0.0f;

    for (int it = 0; it < 16; it++) {
        cp_wait<1>();        // K(it) complete (V(it) may be in flight)
        __syncthreads();

        // ---- S = Q @ K^T : B-frags slot-paired -> LDS.64 on standard sK ----
        float sacc[16][4];
        #pragma unroll
        for (int nt = 0; nt < 16; nt++)
            #pragma unroll
            for (int i = 0; i < 4; i++) sacc[nt][i] = 0.0f;

        #pragma unroll
        for (int kk = 0; kk < 16; kk++) {
            const int colk2 = kk * 8 + 2 * qd;
            #pragma unroll
            for (int nt = 0; nt < 16; nt++) {
                float2 b0 = *(const float2*)(sK + (nt * 8 + group) * FA_PITCH + colk2);
                uint32_t bf[2] = { __float_as_uint(b0.x), __float_as_uint(b0.y) };
                mma_tf32(sacc[nt], qa[kk], bf);
            }
        }
        __syncthreads();
        if (it + 1 < 16) {   // K(it+1) load overlaps softmax + PV
            const float* Kn = Kg + (size_t)(it + 1) * 128 * D_MODEL;
            #pragma unroll
            for (int i = 0; i < 16; i++) {
                int idx = i * 256 + tid;
                int r = idx >> 5, c = (idx & 31) * 4;
                cp16(uK + (uint32_t)(r * FA_PITCH + c) * 4, Kn + (size_t)r * D_MODEL + c);
            }
            cp_commit();
        }

        // ---- online softmax (rows rg / rg+8; lane-quad covers all 8 cols) ----
        float mxa = -1e30f, mxb = -1e30f;
        #pragma unroll
        for (int nt = 0; nt < 16; nt++) {
            sacc[nt][0] *= alpha; sacc[nt][1] *= alpha;
            sacc[nt][2] *= alpha; sacc[nt][3] *= alpha;
            mxa = fmaxf(mxa, fmaxf(sacc[nt][0], sacc[nt][1]));
            mxb = fmaxf(mxb, fmaxf(sacc[nt][2], sacc[nt][3]));
        }
        mxa = fmaxf(mxa, __shfl_xor_sync(0xFFFFFFFF, mxa, 1));
        mxa = fmaxf(mxa, __shfl_xor_sync(0xFFFFFFFF, mxa, 2));
        mxb = fmaxf(mxb, __shfl_xor_sync(0xFFFFFFFF, mxb, 1));
        mxb = fmaxf(mxb, __shfl_xor_sync(0xFFFFFFFF, mxb, 2));
        float na = fmaxf(m0, mxa), nb = fmaxf(m1, mxb);
        float fa_ = __expf(m0 - na), fb_ = __expf(m1 - nb);
        float psa = 0.0f, psb = 0.0f;
        #pragma unroll
        for (int nt = 0; nt < 16; nt++) {
            float e0 = __expf(sacc[nt][0] - na);
            float e1 = __expf(sacc[nt][1] - na);
            float e2 = __expf(sacc[nt][2] - nb);
            float e3 = __expf(sacc[nt][3] - nb);
            psa += e0 + e1;
            psb += e2 + e3;
            sacc[nt][0] = tf32r(e0);   // P (tf32) stays in registers
            sacc[nt][1] = tf32r(e1);
            sacc[nt][2] = tf32r(e2);
            sacc[nt][3] = tf32r(e3);
        }
        psa += __shfl_xor_sync(0xFFFFFFFF, psa, 1);
        psa += __shfl_xor_sync(0xFFFFFFFF, psa, 2);
        psb += __shfl_xor_sync(0xFFFFFFFF, psb, 1);
        psb += __shfl_xor_sync(0xFFFFFFFF, psb, 2);
        l0 = l0 * fa_ + psa; l1 = l1 * fb_ + psb;
        m0 = na; m1 = nb;
        #pragma unroll
        for (int nt = 0; nt < 16; nt++) {
            oacc[nt][0] *= fa_; oacc[nt][1] *= fa_;
            oacc[nt][2] *= fb_; oacc[nt][3] *= fb_;
        }

        if (it + 1 < 16) cp_wait<1>(); else cp_wait<0>();   // V(it) complete
        __syncthreads();

        // ---- O += P @ V : A = sacc C-frag reordered {c0,c2,c1,c3};
        //      B-frags slot-paired -> LDS.64 on standard sV ----
        #pragma unroll
        for (int kk = 0; kk < 16; kk++) {
            uint32_t pa[4] = { __float_as_uint(sacc[kk][0]),
                               __float_as_uint(sacc[kk][2]),
                               __float_as_uint(sacc[kk][1]),
                               __float_as_uint(sacc[kk][3]) };
            const int colk2 = kk * 8 + 2 * qd;
            #pragma unroll
            for (int nt = 0; nt < 16; nt++) {
                float2 b0 = *(const float2*)(sV + (nt * 8 + group) * FA_PITCH + colk2);
                uint32_t bf[2] = { __float_as_uint(b0.x), __float_as_uint(b0.y) };
                mma_tf32(oacc[nt], pa, bf);
            }
        }
        __syncthreads();
        if (it + 1 < 16) {   // V(it+1) load overlaps next QK
            const float* Vn = Vg + (it + 1) * 128;
            #pragma unroll
            for (int i = 0; i < 16; i++) {
                int idx = i * 256 + tid;
                int r = idx >> 5, c = (idx & 31) * 4;
                cp16(uV + (uint32_t)(r * FA_PITCH + c) * 4, Vn + (size_t)r * S_LEN + c);
            }
            cp_commit();
        }
    }

    // finalize: oacc cols d = nt*8 + (2qd, 2qd+1); att written K-PERMUTED
    float inv0 = 1.0f / l0, inv1 = 1.0f / l1;
    int ra = q0 + rg;
    float* outa = att + (size_t)(b * S_LEN + ra) * D_MODEL + h * HDIM;
    float* outb = outa + 8 * (size_t)D_MODEL;
    const int P0 = kperm(2 * qd);
    const int P1 = kperm(2 * qd + 1);
    #pragma unroll
    for (int nt = 0; nt < 16; nt++) {
        int cb = nt * 8;
        outa[cb + P0] = tf32r(oacc[nt][0] * inv0);
        outa[cb + P1] = tf32r(oacc[nt][1] * inv0);
        outb[cb + P0] = tf32r(oacc[nt][2] * inv1);
        outb[cb + P1] = tf32r(oacc[nt][3] * inv1);
    }
}

// ---------------------------------------------------------------------------
// Launch
// ---------------------------------------------------------------------------
extern "C" void kernel_launch(void* const* d_in, const int* in_sizes, int n_in,
                              void* d_out, int out_size) {
    const float* x  = (const float*)d_in[0];
    const float* Wq = (const float*)d_in[1];
    const float* bq = (const float*)d_in[2];
    const float* Wk = (const float*)d_in[3];
    const float* bk = (const float*)d_in[4];
    const float* Wv = (const float*)d_in[5];
    const float* bv = (const float*)d_in[6];
    const float* Wo = (const float*)d_in[7];
    const float* bo = (const float*)d_in[8];
    float* out = (float*)d_out;

    float *q, *k, *vt, *att, *wt;
    cudaGetSymbolAddress((void**)&q,   g_q);
    cudaGetSymbolAddress((void**)&k,   g_k);
    cudaGetSymbolAddress((void**)&vt,  g_vt);
    cudaGetSymbolAddress((void**)&att, g_att);
    cudaGetSymbolAddress((void**)&wt,  g_wt);
    float* wt0 = wt;
    float* wt1 = wt + (size_t)D_MODEL * D_MODEL;
    float* wt2 = wt + 2 * (size_t)D_MODEL * D_MODEL;
    float* wt3 = wt + 3 * (size_t)D_MODEL * D_MODEL;
    float* xr = att;   // att buffer reused as tf32-rounded, K-permuted x

    cudaFuncSetAttribute((const void*)tc_gemm_qkv,
                         cudaFuncAttributeMaxDynamicSharedMemorySize, GEMM_SMEM_SZ);
    cudaFuncSetAttribute((const void*)tc_gemm_o,
                         cudaFuncAttributeMaxDynamicSharedMemorySize, GEMM_SMEM_SZ);
    cudaFuncSetAttribute((const void*)fa_kernel,
                         cudaFuncAttributeMaxDynamicSharedMemorySize, FA_SMEM_SZ);

    // 0. preprocessing: all W^T (permuted); x rounded+permuted; RoPE tables
    dim3 tb(32, 8);
    dim3 tg4(D_MODEL / 32, D_MODEL / 32, 4);
    transpose4_kernel<<<tg4, tb>>>(Wq, Wk, Wv, Wo, wt);
    int nx = NB * S_LEN * D_MODEL;
    round_copy_kernel<<<(nx + 255) / 256, 256>>>(x, xr, nx);
    rope_tables_kernel<<<(S_LEN * HALF_HD + 255) / 256, 256>>>();

    // 1. QKV projections (z=0:Q+RoPE, 1:K+RoPE, 2:V^T) — standard layouts
    dim3 gQKV(D_MODEL / 128, (NB * S_LEN) / 128, 3);    // (16, 32, 3)
    tc_gemm_qkv<<<gQKV, 128, GEMM_SMEM_SZ>>>(xr, wt0, wt1, wt2, bq, bk, bv,
                                             q, k, vt);

    // 2. fused attention (P-in-registers) -> att (K-permuted; overwrites xr)
    dim3 gFA(S_LEN / 128, BH);                          // (16, 32)
    fa_kernel<<<gFA, 256, FA_SMEM_SZ>>>(q, k, vt, att);

    // 3. out = att @ Wo + bo
    dim3 gO(D_MODEL / 128, (NB * S_LEN) / 128);         // (16, 32)
    tc_gemm_o<<<gO, 128, GEMM_SMEM_SZ>>>(att, wt3, bo, out);
}